// round 10
// baseline (speedup 1.0000x reference)
#include <cuda_runtime.h>
#include <math.h>
#include <stdint.h>

#define V_N 100000
#define D_N 300
#define K_N 200
#define B_N 256
#define OUTSTRIDE (K_N + V_N)

typedef unsigned long long u64;

// ---------------- f32x2 packed-math helpers ----------------
__device__ __forceinline__ u64 pack2(float lo, float hi) {
    u64 r;
    asm("mov.b64 %0, {%1, %2};" : "=l"(r)
        : "r"(__float_as_uint(lo)), "r"(__float_as_uint(hi)));
    return r;
}
__device__ __forceinline__ void unpack2(u64 v, float& lo, float& hi) {
    unsigned a, b;
    asm("mov.b64 {%0, %1}, %2;" : "=r"(a), "=r"(b) : "l"(v));
    lo = __uint_as_float(a);
    hi = __uint_as_float(b);
}
__device__ __forceinline__ u64 fma2(u64 a, u64 b, u64 c) {
    u64 d;
    asm("fma.rn.f32x2 %0, %1, %2, %3;" : "=l"(d) : "l"(a), "l"(b), "l"(c));
    return d;
}

// ---------------- scratch (static device globals; no runtime alloc) ----------------
__device__ float g_logp[(size_t)K_N * V_N];     // 80 MB, layout [K][V]
// packed [d/2][K][2] layouts: element (d,k) at (d/2)*2K + k*2 + (d&1)
__device__ float g_dinvP[D_N * K_N];
__device__ float g_m2P  [D_N * K_N];            // -2 * mu * Dinv
__device__ float g_uP   [D_N * K_N];            // cov_factor * Dinv
__device__ float g_c1[K_N], g_c2[K_N], g_capinv[K_N], g_constk[K_N];
__device__ float g_softc[K_N];                  // m_k + log(S_k)
__device__ float g_pmax[K_N * 8];               // per-chunk max
__device__ float g_psum[K_N * 8];               // per-chunk sum (local-max referenced)
__device__ float g_sxT[K_N * B_N];              // sampled_x transposed [K][B]

// ---------------- kernel 1: per-topic precompute ----------------
__global__ void topic_prep(const float* __restrict__ mu,
                           const float* __restrict__ cf,
                           const float* __restrict__ cd) {
    int k = blockIdx.x;
    int tid = threadIdx.x;
    float capa = 0.f, ld = 0.f, c1 = 0.f, c2 = 0.f;
    for (int d = tid; d < D_N; d += blockDim.x) {
        float diag = cd[k * D_N + d];
        float dinv = 1.0f / diag;
        float m    = mu[k * D_N + d];
        float w    = cf[k * D_N + d];
        float u    = w * dinv;
        float mdi  = m * dinv;
        int pidx = (d >> 1) * (2 * K_N) + k * 2 + (d & 1);
        g_dinvP[pidx] = dinv;
        g_m2P  [pidx] = -2.0f * mdi;
        g_uP   [pidx] = u;
        capa += w * u;
        ld   += logf(diag);
        c1   += m * mdi;
        c2   += m * u;
    }
    __shared__ float s[4][128];
    s[0][tid] = capa; s[1][tid] = ld; s[2][tid] = c1; s[3][tid] = c2;
    __syncthreads();
    for (int off = 64; off > 0; off >>= 1) {
        if (tid < off) {
            s[0][tid] += s[0][tid + off];
            s[1][tid] += s[1][tid + off];
            s[2][tid] += s[2][tid + off];
            s[3][tid] += s[3][tid + off];
        }
        __syncthreads();
    }
    if (tid == 0) {
        float cap    = 1.0f + s[0][0];
        float logdet = s[1][0] + logf(cap);
        g_c1[k]     = s[2][0];
        g_c2[k]     = s[3][0];
        g_capinv[k] = 1.0f / cap;
        const float LOG2PI = 1.8378770664093453f;
        g_constk[k] = -0.5f * ((float)D_N * LOG2PI + logdet);
    }
}

// ---------------- kernel 2: copy sampled_x into out[:, :K] + transpose ----------------
__global__ void sx_prep(const float* __restrict__ sx, float* __restrict__ out) {
    int idx = blockIdx.x * blockDim.x + threadIdx.x;
    if (idx < B_N * K_N) {
        int b = idx / K_N, k = idx % K_N;
        float v = sx[idx];
        out[(size_t)b * OUTSTRIDE + k] = v;
        g_sxT[k * B_N + b] = v;
    }
}

// ---------------- kernel 3: logp (V x K), f32x2 packed across d-pairs ----------------
#define MV 128
#define NK 40
#define DP (D_N / 2)                           // 150 d-pairs
#define SROW (NK * 2)                          // 80 floats per d-pair row
#define SARR (DP * SROW)                       // 12000 floats per array
#define SMEM_LOGP (3 * SARR * sizeof(float))   // 144 KB

__global__ __launch_bounds__(256) void logp_kernel(const float* __restrict__ wv) {
    extern __shared__ float smem[];
    float* s_d = smem;               // dinv pairs
    float* s_m = smem + SARR;        // -2*mdi pairs
    float* s_u = smem + 2 * SARR;    // u pairs

    const int k0 = blockIdx.x * NK;  // k inner in grid -> L2 reuse of word rows
    const int v0 = blockIdx.y * MV;
    const int tid = threadIdx.x;

    // stage packed topic slices: global row per dp = 2*K_N floats; slice 80 floats
    for (int e = tid; e < SARR; e += 256) {
        int dp  = e / SROW;
        int off = e - dp * SROW;
        int g   = dp * (2 * K_N) + k0 * 2 + off;
        s_d[e] = g_dinvP[g];
        s_m[e] = g_m2P[g];
        s_u[e] = g_uP[g];
    }
    __syncthreads();

    const int tv = tid & 31;   // 0..31 word group
    const int tk = tid >> 5;   // 0..7 topic group (uniform per warp -> smem broadcast)
    const int kb = tk * 5;

    u64 accqm[4][5], accu[4][5];
#pragma unroll
    for (int i = 0; i < 4; i++)
#pragma unroll
        for (int j = 0; j < 5; j++) { accqm[i][j] = 0ull; accu[i][j] = 0ull; }

    const int vbase = v0 + tv * 4;   // multiple of 4; V_N % 4 == 0
    const bool vvalid = (vbase < V_N);

    for (int d0 = 0; d0 < D_N; d0 += 4) {
        float4 w4[4];
#pragma unroll
        for (int i = 0; i < 4; i++) {
            w4[i] = vvalid
                ? *reinterpret_cast<const float4*>(wv + (size_t)(vbase + i) * D_N + d0)
                : make_float4(0.f, 0.f, 0.f, 0.f);
        }
#pragma unroll
        for (int h = 0; h < 2; h++) {          // two d-pairs per float4
            const int dp = (d0 >> 1) + h;
            u64 wp[4];
#pragma unroll
            for (int i = 0; i < 4; i++)
                wp[i] = h ? pack2(w4[i].z, w4[i].w) : pack2(w4[i].x, w4[i].y);

            const u64* pd = reinterpret_cast<const u64*>(s_d + dp * SROW + kb * 2);
            const u64* pm = reinterpret_cast<const u64*>(s_m + dp * SROW + kb * 2);
            const u64* pu = reinterpret_cast<const u64*>(s_u + dp * SROW + kb * 2);
#pragma unroll
            for (int j = 0; j < 5; j++) {
                u64 dv = pd[j];
                u64 mm = pm[j];
                u64 uu = pu[j];
#pragma unroll
                for (int i = 0; i < 4; i++) {
                    u64 inner = fma2(wp[i], dv, mm);            // w*dinv - 2*mdi
                    accqm[i][j] = fma2(wp[i], inner, accqm[i][j]); // += w^2*dinv - 2*w*mdi
                    accu[i][j]  = fma2(wp[i], uu, accu[i][j]);     // += w*u
                }
            }
        }
    }

    if (vvalid) {
#pragma unroll
        for (int j = 0; j < 5; j++) {
            int k = k0 + kb + j;
            float c1 = g_c1[k], c2 = g_c2[k], ci = g_capinv[k], ck = g_constk[k];
            float r[4];
#pragma unroll
            for (int i = 0; i < 4; i++) {
                float qa, qb, ta, tb;
                unpack2(accqm[i][j], qa, qb);
                unpack2(accu[i][j], ta, tb);
                float q = qa + qb + c1;
                float t = ta + tb - c2;
                r[i] = ck - 0.5f * (q - t * t * ci);
            }
            *reinterpret_cast<float4*>(&g_logp[(size_t)k * V_N + vbase]) =
                make_float4(r[0], r[1], r[2], r[3]);
        }
    }
}

// ---------------- kernel 4a: per-(topic, chunk) partial max/sum ----------------
#define NCH 8
#define CHV (V_N / NCH)   // 12500, divisible by 4

__global__ void softmax_partial() {
    const int k = blockIdx.x;
    const int c = blockIdx.y;
    const int tid = threadIdx.x;
    const float4* p = reinterpret_cast<const float4*>(&g_logp[(size_t)k * V_N + c * CHV]);
    const int n4 = CHV / 4;

    float m = -3.4e38f;
    for (int f = tid; f < n4; f += 256) {
        float4 x = p[f];
        m = fmaxf(m, fmaxf(fmaxf(x.x, x.y), fmaxf(x.z, x.w)));
    }
    __shared__ float red[256];
    red[tid] = m;
    __syncthreads();
    for (int off = 128; off > 0; off >>= 1) {
        if (tid < off) red[tid] = fmaxf(red[tid], red[tid + off]);
        __syncthreads();
    }
    float M = red[0];
    __syncthreads();

    float s = 0.f;
    for (int f = tid; f < n4; f += 256) {
        float4 x = p[f];
        s += __expf(x.x - M) + __expf(x.y - M) + __expf(x.z - M) + __expf(x.w - M);
    }
    red[tid] = s;
    __syncthreads();
    for (int off = 128; off > 0; off >>= 1) {
        if (tid < off) red[tid] += red[tid + off];
        __syncthreads();
    }
    if (tid == 0) {
        g_pmax[k * NCH + c] = M;
        g_psum[k * NCH + c] = red[0];
    }
}

// ---------------- kernel 4b: merge partials -> g_softc ----------------
__global__ void softmax_merge() {
    int k = blockIdx.x * blockDim.x + threadIdx.x;
    if (k < K_N) {
        float M = -3.4e38f;
#pragma unroll
        for (int c = 0; c < NCH; c++) M = fmaxf(M, g_pmax[k * NCH + c]);
        float S = 0.f;
#pragma unroll
        for (int c = 0; c < NCH; c++)
            S += g_psum[k * NCH + c] * __expf(g_pmax[k * NCH + c] - M);
        g_softc[k] = M + logf(S);
    }
}

// ---------------- kernel 5: word_dist = sx @ softmax(logp), f32x2 over v ----------------
#define VT 64
#define BT 64
#define KC 8

__global__ __launch_bounds__(256) void out_gemm(float* __restrict__ out) {
    __shared__ float wt [KC][VT];   // exp-normalized P tile
    __shared__ float sxs[KC][BT];

    const int v0 = blockIdx.x * VT;
    const int b0 = blockIdx.y * BT;
    const int tid = threadIdx.x;
    const int tv = tid & 15;        // 16 v-groups of 4
    const int tb = tid >> 4;        // 16 b-groups of 4

    u64 acc[4][2];                  // [jb][v-pair]
#pragma unroll
    for (int a = 0; a < 4; a++) { acc[a][0] = 0ull; acc[a][1] = 0ull; }

    for (int kc = 0; kc < K_N; kc += KC) {
        __syncthreads();
#pragma unroll
        for (int r = 0; r < 2; r++) {
            int e = tid + r * 256;
            int kk = e >> 6, vv = e & 63;
            int k = kc + kk;
            int v = v0 + vv;
            float x = (v < V_N) ? g_logp[(size_t)k * V_N + v] : -3.0e38f;
            wt[kk][vv] = __expf(x - g_softc[k]);   // normalized probability
        }
#pragma unroll
        for (int r = 0; r < 2; r++) {
            int e = tid + r * 256;
            int kk = e >> 6, bb = e & 63;
            sxs[kk][bb] = g_sxT[(kc + kk) * B_N + b0 + bb];
        }
        __syncthreads();
#pragma unroll
        for (int kk = 0; kk < KC; kk++) {
            const u64* ap = reinterpret_cast<const u64*>(&wt[kk][tv * 4]);
            u64 a0 = ap[0], a1 = ap[1];
            float4 s4 = *reinterpret_cast<const float4*>(&sxs[kk][tb * 4]);
            u64 sd0 = pack2(s4.x, s4.x);
            u64 sd1 = pack2(s4.y, s4.y);
            u64 sd2 = pack2(s4.z, s4.z);
            u64 sd3 = pack2(s4.w, s4.w);
            acc[0][0] = fma2(sd0, a0, acc[0][0]); acc[0][1] = fma2(sd0, a1, acc[0][1]);
            acc[1][0] = fma2(sd1, a0, acc[1][0]); acc[1][1] = fma2(sd1, a1, acc[1][1]);
            acc[2][0] = fma2(sd2, a0, acc[2][0]); acc[2][1] = fma2(sd2, a1, acc[2][1]);
            acc[3][0] = fma2(sd3, a0, acc[3][0]); acc[3][1] = fma2(sd3, a1, acc[3][1]);
        }
    }

    const int vw = v0 + tv * 4;
    if (vw < V_N) {
#pragma unroll
        for (int jb = 0; jb < 4; jb++) {
            int b = b0 + tb * 4 + jb;
            float r0, r1, r2, r3;
            unpack2(acc[jb][0], r0, r1);
            unpack2(acc[jb][1], r2, r3);
            *reinterpret_cast<float4*>(&out[(size_t)b * OUTSTRIDE + K_N + vw]) =
                make_float4(r0, r1, r2, r3);
        }
    }
}

// ---------------- launch ----------------
extern "C" void kernel_launch(void* const* d_in, const int* in_sizes, int n_in,
                              void* d_out, int out_size) {
    const float* sx = (const float*)d_in[0];   // (256, 200)
    const float* wv = (const float*)d_in[1];   // (100000, 300)
    const float* mu = (const float*)d_in[2];   // (200, 300)
    const float* cf = (const float*)d_in[3];   // (200, 300)
    const float* cd = (const float*)d_in[4];   // (200, 300)
    float* out = (float*)d_out;                // (256, 100200)

    cudaFuncSetAttribute(logp_kernel, cudaFuncAttributeMaxDynamicSharedMemorySize,
                         (int)SMEM_LOGP);

    topic_prep<<<K_N, 128>>>(mu, cf, cd);
    sx_prep<<<(B_N * K_N + 255) / 256, 256>>>(sx, out);
    logp_kernel<<<dim3(K_N / NK, (V_N + MV - 1) / MV), 256, SMEM_LOGP>>>(wv);
    softmax_partial<<<dim3(K_N, NCH), 256>>>();
    softmax_merge<<<1, 256>>>();
    out_gemm<<<dim3((V_N + VT - 1) / VT, B_N / BT), 256>>>(out);
}

// round 11
// speedup vs baseline: 1.2738x; 1.2738x over previous
#include <cuda_runtime.h>
#include <math.h>
#include <stdint.h>

#define V_N 100000
#define D_N 300
#define K_N 200
#define B_N 256
#define OUTSTRIDE (K_N + V_N)

typedef unsigned long long u64;

// ---------------- f32x2 packed-math helpers ----------------
__device__ __forceinline__ u64 pack2(float lo, float hi) {
    u64 r;
    asm("mov.b64 %0, {%1, %2};" : "=l"(r)
        : "r"(__float_as_uint(lo)), "r"(__float_as_uint(hi)));
    return r;
}
__device__ __forceinline__ void unpack2(u64 v, float& lo, float& hi) {
    unsigned a, b;
    asm("mov.b64 {%0, %1}, %2;" : "=r"(a), "=r"(b) : "l"(v));
    lo = __uint_as_float(a);
    hi = __uint_as_float(b);
}
__device__ __forceinline__ u64 fma2(u64 a, u64 b, u64 c) {
    u64 d;
    asm("fma.rn.f32x2 %0, %1, %2, %3;" : "=l"(d) : "l"(a), "l"(b), "l"(c));
    return d;
}

// ---------------- scratch (static device globals; no runtime alloc) ----------------
__device__ float g_logp[(size_t)K_N * V_N];     // 80 MB, layout [K][V]
// packed [d/2][K][2] layouts: element (d,k) at (d/2)*2K + k*2 + (d&1)
__device__ float g_dinvP[D_N * K_N];
__device__ float g_m2P  [D_N * K_N];            // -2 * mu * Dinv
__device__ float g_uP   [D_N * K_N];            // cov_factor * Dinv
__device__ float g_c1[K_N], g_c2[K_N], g_capinv[K_N], g_constk[K_N];
__device__ float g_softc[K_N];                  // m_k + log(S_k)
__device__ float g_pmax[K_N * 8];               // per-chunk max
__device__ float g_psum[K_N * 8];               // per-chunk sum (local-max referenced)
__device__ float g_sxT[K_N * B_N];              // sampled_x transposed [K][B]

// ---------------- kernel 1: per-topic precompute ----------------
__global__ void topic_prep(const float* __restrict__ mu,
                           const float* __restrict__ cf,
                           const float* __restrict__ cd) {
    int k = blockIdx.x;
    int tid = threadIdx.x;
    float capa = 0.f, ld = 0.f, c1 = 0.f, c2 = 0.f;
    for (int d = tid; d < D_N; d += blockDim.x) {
        float diag = cd[k * D_N + d];
        float dinv = 1.0f / diag;
        float m    = mu[k * D_N + d];
        float w    = cf[k * D_N + d];
        float u    = w * dinv;
        float mdi  = m * dinv;
        int pidx = (d >> 1) * (2 * K_N) + k * 2 + (d & 1);
        g_dinvP[pidx] = dinv;
        g_m2P  [pidx] = -2.0f * mdi;
        g_uP   [pidx] = u;
        capa += w * u;
        ld   += logf(diag);
        c1   += m * mdi;
        c2   += m * u;
    }
    __shared__ float s[4][128];
    s[0][tid] = capa; s[1][tid] = ld; s[2][tid] = c1; s[3][tid] = c2;
    __syncthreads();
    for (int off = 64; off > 0; off >>= 1) {
        if (tid < off) {
            s[0][tid] += s[0][tid + off];
            s[1][tid] += s[1][tid + off];
            s[2][tid] += s[2][tid + off];
            s[3][tid] += s[3][tid + off];
        }
        __syncthreads();
    }
    if (tid == 0) {
        float cap    = 1.0f + s[0][0];
        float logdet = s[1][0] + logf(cap);
        g_c1[k]     = s[2][0];
        g_c2[k]     = s[3][0];
        g_capinv[k] = 1.0f / cap;
        const float LOG2PI = 1.8378770664093453f;
        g_constk[k] = -0.5f * ((float)D_N * LOG2PI + logdet);
    }
}

// ---------------- kernel 2: copy sampled_x into out[:, :K] + transpose ----------------
__global__ void sx_prep(const float* __restrict__ sx, float* __restrict__ out) {
    int idx = blockIdx.x * blockDim.x + threadIdx.x;
    if (idx < B_N * K_N) {
        int b = idx / K_N, k = idx % K_N;
        float v = sx[idx];
        out[(size_t)b * OUTSTRIDE + k] = v;
        g_sxT[k * B_N + b] = v;
    }
}

// ---------------- kernel 3: logp (V x K), f32x2, 512 threads / 16 warps ----------------
#define MV 256
#define NK 40
#define DP (D_N / 2)                           // 150 d-pairs
#define SROW (NK * 2)                          // 80 floats per d-pair row
#define SARR (DP * SROW)                       // 12000 floats per array
#define SMEM_LOGP (3 * SARR * sizeof(float))   // 144 KB

__global__ __launch_bounds__(512, 1) void logp_kernel(const float* __restrict__ wv) {
    extern __shared__ float smem[];
    float* s_d = smem;               // dinv pairs
    float* s_m = smem + SARR;        // -2*mdi pairs
    float* s_u = smem + 2 * SARR;    // u pairs

    const int k0 = blockIdx.x * NK;  // k inner in grid -> L2 reuse of word rows
    const int v0 = blockIdx.y * MV;
    const int tid = threadIdx.x;

    // stage packed topic slices: global row per dp = 2*K_N floats; slice 80 floats
    for (int e = tid; e < SARR; e += 512) {
        int dp  = e / SROW;
        int off = e - dp * SROW;
        int g   = dp * (2 * K_N) + k0 * 2 + off;
        s_d[e] = g_dinvP[g];
        s_m[e] = g_m2P[g];
        s_u[e] = g_uP[g];
    }
    __syncthreads();

    const int tv = tid & 63;   // 0..63 word group (x4 rows = 256 words per block)
    const int tk = tid >> 6;   // 0..7 topic group (uniform per warp-half granularity)
    const int kb = tk * 5;

    u64 accqm[4][5], accu[4][5];
#pragma unroll
    for (int i = 0; i < 4; i++)
#pragma unroll
        for (int j = 0; j < 5; j++) { accqm[i][j] = 0ull; accu[i][j] = 0ull; }

    const int vbase = v0 + tv * 4;   // multiple of 4; V_N % 4 == 0
    const bool vvalid = (vbase < V_N);

    for (int d0 = 0; d0 < D_N; d0 += 4) {
        float4 w4[4];
#pragma unroll
        for (int i = 0; i < 4; i++) {
            w4[i] = vvalid
                ? *reinterpret_cast<const float4*>(wv + (size_t)(vbase + i) * D_N + d0)
                : make_float4(0.f, 0.f, 0.f, 0.f);
        }
#pragma unroll
        for (int h = 0; h < 2; h++) {          // two d-pairs per float4
            const int dp = (d0 >> 1) + h;
            u64 wp[4];
#pragma unroll
            for (int i = 0; i < 4; i++)
                wp[i] = h ? pack2(w4[i].z, w4[i].w) : pack2(w4[i].x, w4[i].y);

            const u64* pd = reinterpret_cast<const u64*>(s_d + dp * SROW + kb * 2);
            const u64* pm = reinterpret_cast<const u64*>(s_m + dp * SROW + kb * 2);
            const u64* pu = reinterpret_cast<const u64*>(s_u + dp * SROW + kb * 2);
#pragma unroll
            for (int j = 0; j < 5; j++) {
                u64 dv = pd[j];
                u64 mm = pm[j];
                u64 uu = pu[j];
#pragma unroll
                for (int i = 0; i < 4; i++) {
                    u64 inner = fma2(wp[i], dv, mm);               // w*dinv - 2*mdi
                    accqm[i][j] = fma2(wp[i], inner, accqm[i][j]); // += w^2*dinv - 2*w*mdi
                    accu[i][j]  = fma2(wp[i], uu, accu[i][j]);     // += w*u
                }
            }
        }
    }

    if (vvalid) {
#pragma unroll
        for (int j = 0; j < 5; j++) {
            int k = k0 + kb + j;
            float c1 = g_c1[k], c2 = g_c2[k], ci = g_capinv[k], ck = g_constk[k];
            float r[4];
#pragma unroll
            for (int i = 0; i < 4; i++) {
                float qa, qb, ta, tb;
                unpack2(accqm[i][j], qa, qb);
                unpack2(accu[i][j], ta, tb);
                float q = qa + qb + c1;
                float t = ta + tb - c2;
                r[i] = ck - 0.5f * (q - t * t * ci);
            }
            *reinterpret_cast<float4*>(&g_logp[(size_t)k * V_N + vbase]) =
                make_float4(r[0], r[1], r[2], r[3]);
        }
    }
}

// ---------------- kernel 4a: per-(topic, chunk) partial max/sum ----------------
#define NCH 8
#define CHV (V_N / NCH)   // 12500, divisible by 4

__global__ void softmax_partial() {
    const int k = blockIdx.x;
    const int c = blockIdx.y;
    const int tid = threadIdx.x;
    const float4* p = reinterpret_cast<const float4*>(&g_logp[(size_t)k * V_N + c * CHV]);
    const int n4 = CHV / 4;

    float m = -3.4e38f;
    for (int f = tid; f < n4; f += 256) {
        float4 x = p[f];
        m = fmaxf(m, fmaxf(fmaxf(x.x, x.y), fmaxf(x.z, x.w)));
    }
    __shared__ float red[256];
    red[tid] = m;
    __syncthreads();
    for (int off = 128; off > 0; off >>= 1) {
        if (tid < off) red[tid] = fmaxf(red[tid], red[tid + off]);
        __syncthreads();
    }
    float M = red[0];
    __syncthreads();

    float s = 0.f;
    for (int f = tid; f < n4; f += 256) {
        float4 x = p[f];
        s += __expf(x.x - M) + __expf(x.y - M) + __expf(x.z - M) + __expf(x.w - M);
    }
    red[tid] = s;
    __syncthreads();
    for (int off = 128; off > 0; off >>= 1) {
        if (tid < off) red[tid] += red[tid + off];
        __syncthreads();
    }
    if (tid == 0) {
        g_pmax[k * NCH + c] = M;
        g_psum[k * NCH + c] = red[0];
    }
}

// ---------------- kernel 4b: merge partials -> g_softc ----------------
__global__ void softmax_merge() {
    int k = blockIdx.x * blockDim.x + threadIdx.x;
    if (k < K_N) {
        float M = -3.4e38f;
#pragma unroll
        for (int c = 0; c < NCH; c++) M = fmaxf(M, g_pmax[k * NCH + c]);
        float S = 0.f;
#pragma unroll
        for (int c = 0; c < NCH; c++)
            S += g_psum[k * NCH + c] * __expf(g_pmax[k * NCH + c] - M);
        g_softc[k] = M + logf(S);
    }
}

// ---------------- kernel 5: word_dist = sx @ softmax(logp), f32x2 over v ----------------
#define VT 64
#define BT 64
#define KC 8

__global__ __launch_bounds__(256) void out_gemm(float* __restrict__ out) {
    __shared__ float wt [KC][VT];   // exp-normalized P tile
    __shared__ float sxs[KC][BT];

    // b-dim is grid.x (fastest) so the 4 blocks sharing a logp tile are
    // schedule-adjacent -> L2 reuse of g_logp
    const int b0 = blockIdx.x * BT;
    const int v0 = blockIdx.y * VT;
    const int tid = threadIdx.x;
    const int tv = tid & 15;        // 16 v-groups of 4
    const int tb = tid >> 4;        // 16 b-groups of 4

    u64 acc[4][2];                  // [jb][v-pair]
#pragma unroll
    for (int a = 0; a < 4; a++) { acc[a][0] = 0ull; acc[a][1] = 0ull; }

    for (int kc = 0; kc < K_N; kc += KC) {
        __syncthreads();
#pragma unroll
        for (int r = 0; r < 2; r++) {
            int e = tid + r * 256;
            int kk = e >> 6, vv = e & 63;
            int k = kc + kk;
            int v = v0 + vv;
            float x = (v < V_N) ? g_logp[(size_t)k * V_N + v] : -3.0e38f;
            wt[kk][vv] = __expf(x - g_softc[k]);   // normalized probability
        }
#pragma unroll
        for (int r = 0; r < 2; r++) {
            int e = tid + r * 256;
            int kk = e >> 6, bb = e & 63;
            sxs[kk][bb] = g_sxT[(kc + kk) * B_N + b0 + bb];
        }
        __syncthreads();
#pragma unroll
        for (int kk = 0; kk < KC; kk++) {
            const u64* ap = reinterpret_cast<const u64*>(&wt[kk][tv * 4]);
            u64 a0 = ap[0], a1 = ap[1];
            float4 s4 = *reinterpret_cast<const float4*>(&sxs[kk][tb * 4]);
            u64 sd0 = pack2(s4.x, s4.x);
            u64 sd1 = pack2(s4.y, s4.y);
            u64 sd2 = pack2(s4.z, s4.z);
            u64 sd3 = pack2(s4.w, s4.w);
            acc[0][0] = fma2(sd0, a0, acc[0][0]); acc[0][1] = fma2(sd0, a1, acc[0][1]);
            acc[1][0] = fma2(sd1, a0, acc[1][0]); acc[1][1] = fma2(sd1, a1, acc[1][1]);
            acc[2][0] = fma2(sd2, a0, acc[2][0]); acc[2][1] = fma2(sd2, a1, acc[2][1]);
            acc[3][0] = fma2(sd3, a0, acc[3][0]); acc[3][1] = fma2(sd3, a1, acc[3][1]);
        }
    }

    const int vw = v0 + tv * 4;
    if (vw < V_N) {
#pragma unroll
        for (int jb = 0; jb < 4; jb++) {
            int b = b0 + tb * 4 + jb;
            float r0, r1, r2, r3;
            unpack2(acc[jb][0], r0, r1);
            unpack2(acc[jb][1], r2, r3);
            *reinterpret_cast<float4*>(&out[(size_t)b * OUTSTRIDE + K_N + vw]) =
                make_float4(r0, r1, r2, r3);
        }
    }
}

// ---------------- launch ----------------
extern "C" void kernel_launch(void* const* d_in, const int* in_sizes, int n_in,
                              void* d_out, int out_size) {
    const float* sx = (const float*)d_in[0];   // (256, 200)
    const float* wv = (const float*)d_in[1];   // (100000, 300)
    const float* mu = (const float*)d_in[2];   // (200, 300)
    const float* cf = (const float*)d_in[3];   // (200, 300)
    const float* cd = (const float*)d_in[4];   // (200, 300)
    float* out = (float*)d_out;                // (256, 100200)

    cudaFuncSetAttribute(logp_kernel, cudaFuncAttributeMaxDynamicSharedMemorySize,
                         (int)SMEM_LOGP);

    topic_prep<<<K_N, 128>>>(mu, cf, cd);
    sx_prep<<<(B_N * K_N + 255) / 256, 256>>>(sx, out);
    logp_kernel<<<dim3(K_N / NK, (V_N + MV - 1) / MV), 512, SMEM_LOGP>>>(wv);
    softmax_partial<<<dim3(K_N, NCH), 256>>>();
    softmax_merge<<<1, 256>>>();
    out_gemm<<<dim3(B_N / BT, (V_N + VT - 1) / VT), 256>>>(out);
}